// round 1
// baseline (speedup 1.0000x reference)
#include <cuda_runtime.h>
#include <cmath>

#define N_NODES 12500
#define N_EDGES 200000
#define OUT_ELEMS (N_NODES * 64)

// shared memory layout (in floats)
#define W2T_STRIDE 20                    // 16 k-values padded to 20 floats (80B, 16B aligned, bank-conflict-free)
#define SM_W2T 0                         // 1024 rows * 20 = 20480 floats
#define SM_B2  (1024 * W2T_STRIDE)       // 20480
#define SM_W1  (SM_B2 + 1024)            // 21504
#define SM_B1  (SM_W1 + 256)             // 21760
#define SM_TOT (SM_B1 + 16)              // 21776 floats = 87104 bytes

__device__ int   g_src[N_EDGES];
__device__ int   g_dst[N_EDGES];
__device__ float g_counts[N_NODES];
__device__ int   g_is64;

// ---------------------------------------------------------------------------
// edge_index dtype detection: if input is int64 (little-endian), the high
// 32-bit word of every value is 0 (indices in [0, 12500)). If it is int32,
// 128 consecutive zero words is essentially impossible.
// ---------------------------------------------------------------------------
__global__ void detect_kernel(const unsigned* __restrict__ ei) {
    if (blockIdx.x == 0 && threadIdx.x == 0) {
        int ok = 1;
        for (int i = 0; i < 128; i++) ok &= (ei[2 * i + 1] == 0u);
        g_is64 = ok;
    }
}

// zero output + counts, convert edge_index to int32 scratch
__global__ void prep_kernel(const int* __restrict__ ei, float* __restrict__ out) {
    int i = blockIdx.x * blockDim.x + threadIdx.x;
    if (i < OUT_ELEMS) out[i] = 0.f;
    if (i < N_NODES) g_counts[i] = 0.f;
    if (i < N_EDGES) {
        if (g_is64) {
            g_src[i] = ei[2 * i];                  // low word of int64
            g_dst[i] = ei[2 * (N_EDGES + i)];
        } else {
            g_src[i] = ei[i];
            g_dst[i] = ei[N_EDGES + i];
        }
    }
}

// ---------------------------------------------------------------------------
// Main kernel: one warp processes 2 edges per pass.
//   lane = 0..31, w = lane&15 (output column), lanes 0-15 -> weight blocks 0,1
//   lanes 16-31 -> weight blocks 2,3.  For each u (0..15):
//     wv_b[w] = b2[b,u,w] + sum_k h[k] * w2[k,b,u,w]      (fused, W never stored)
//     acc += coeff[u] * wv_b[w]
//   Coefficients (c0 = x0*y0, z = x1·y1, x0, x1[:,i]) live in lane u (low half)
//   and lane u+16 (high half) and are broadcast with one SHFL.IDX each.
// ---------------------------------------------------------------------------
__global__ void __launch_bounds__(256, 2) conv_kernel(
    const float*  __restrict__ node_attr,
    const float*  __restrict__ edge_attr,
    const float4* __restrict__ edge_sh4,
    const float*  __restrict__ w1,
    const float*  __restrict__ b1,
    const float*  __restrict__ w2,
    const float*  __restrict__ b2,
    float*        __restrict__ out)
{
    extern __shared__ float sm[];

    // stage weights: w2 transposed to k-contiguous rows w2t[j][k], j = b*256+u*16+w
    for (int i = threadIdx.x; i < 16 * 1024; i += 256) {
        int k = i >> 10, j = i & 1023;          // coalesced read of w2[k][j]
        sm[SM_W2T + j * W2T_STRIDE + k] = w2[i];
    }
    for (int i = threadIdx.x; i < 1024; i += 256) sm[SM_B2 + i] = b2[i];
    if (threadIdx.x < 256) sm[SM_W1 + threadIdx.x] = w1[threadIdx.x];
    if (threadIdx.x < 16)  sm[SM_B1 + threadIdx.x] = b1[threadIdx.x];
    __syncthreads();

    const int lane = threadIdx.x & 31;
    const int wv   = lane & 15;
    const int hi16 = lane & 16;                  // 0 for blocks {0,1}, 16 for {2,3}

    const float* pA  = sm + SM_W2T + (((hi16 ? 2 : 0) * 256) + wv) * W2T_STRIDE;
    const float* b2A = sm + SM_B2 + (hi16 ? 512 : 0) + wv;

    const float alpha = 0.17677669529663688f;    // 1/sqrt(32)
    const float inv3  = 0.57735026918962576f;    // 1/sqrt(3)

    const int warpsTotal = gridDim.x * (blockDim.x >> 5);
    const int gw = blockIdx.x * (blockDim.x >> 5) + (threadIdx.x >> 5);

    for (int p = gw; p < N_EDGES / 2; p += warpsTotal) {
        const int e0 = 2 * p, e1 = 2 * p + 1;
        const int s0 = g_src[e0], d0 = g_dst[e0];
        const int s1 = g_src[e1], d1 = g_dst[e1];
        const float4 sh0 = edge_sh4[e0];
        const float4 sh1 = edge_sh4[e1];

        // ---- h = silu(edge_attr @ w1 + b1), lane k computes h[k] ----
        float ea0 = edge_attr[e0 * 16 + wv];
        float ea1 = edge_attr[e1 * 16 + wv];
        float t0 = sm[SM_B1 + wv], t1 = t0;
        #pragma unroll
        for (int j = 0; j < 16; j++) {
            float wj = sm[SM_W1 + j * 16 + wv];
            t0 = fmaf(__shfl_sync(0xffffffffu, ea0, j), wj, t0);
            t1 = fmaf(__shfl_sync(0xffffffffu, ea1, j), wj, t1);
        }
        float h0 = t0 / (1.f + __expf(-t0));
        float h1 = t1 / (1.f + __expf(-t1));

        // broadcast full h vectors into registers
        float h0r[16], h1r[16];
        #pragma unroll
        for (int m = 0; m < 16; m++) {
            h0r[m] = __shfl_sync(0xffffffffu, h0, m);
            h1r[m] = __shfl_sync(0xffffffffu, h1, m);
        }

        // ---- gather node features, build per-u coefficient registers ----
        const float* n0 = node_attr + (size_t)s0 * 64;
        const float* n1 = node_attr + (size_t)s1 * 64;
        float x0_0 = n0[wv];
        float x1a_0 = n0[16 + 3 * wv], x1b_0 = n0[17 + 3 * wv], x1c_0 = n0[18 + 3 * wv];
        float x0_1 = n1[wv];
        float x1a_1 = n1[16 + 3 * wv], x1b_1 = n1[17 + 3 * wv], x1c_1 = n1[18 + 3 * wv];

        float rA0, rB1_0, rB2_0, rB3_0, rA1, rB1_1, rB2_1, rB3_1;
        if (!hi16) {  // low half holds c0[u] = x0*y0 and z[u] = x1·y1
            rA0  = x0_0 * sh0.x;
            rB1_0 = fmaf(x1a_0, sh0.y, fmaf(x1b_0, sh0.z, x1c_0 * sh0.w));
            rB2_0 = 0.f; rB3_0 = 0.f;
            rA1  = x0_1 * sh1.x;
            rB1_1 = fmaf(x1a_1, sh1.y, fmaf(x1b_1, sh1.z, x1c_1 * sh1.w));
            rB2_1 = 0.f; rB3_1 = 0.f;
        } else {      // high half holds x0[u] and x1[u, 0..2]
            rA0 = x0_0; rB1_0 = x1a_0; rB2_0 = x1b_0; rB3_0 = x1c_0;
            rA1 = x0_1; rB1_1 = x1a_1; rB2_1 = x1b_1; rB3_1 = x1c_1;
        }

        float a00 = 0.f, a10 = 0.f, a20 = 0.f, a30 = 0.f;
        float a01 = 0.f, a11 = 0.f, a21 = 0.f, a31 = 0.f;

        #pragma unroll
        for (int u = 0; u < 16; u++) {
            const int srcLane = u + hi16;
            float s00 = __shfl_sync(0xffffffffu, rA0,  srcLane);
            float s10 = __shfl_sync(0xffffffffu, rB1_0, srcLane);
            float s20 = __shfl_sync(0xffffffffu, rB2_0, srcLane);
            float s30 = __shfl_sync(0xffffffffu, rB3_0, srcLane);
            float s01 = __shfl_sync(0xffffffffu, rA1,  srcLane);
            float s11 = __shfl_sync(0xffffffffu, rB1_1, srcLane);
            float s21 = __shfl_sync(0xffffffffu, rB2_1, srcLane);
            float s31 = __shfl_sync(0xffffffffu, rB3_1, srcLane);

            float bA = b2A[u * 16];
            float bB = b2A[256 + u * 16];
            float wA0 = bA, wA1 = bA, wB0 = bB, wB1 = bB;

            const float4* qA = (const float4*)(pA + u * 16 * W2T_STRIDE);
            const float4* qB = (const float4*)(pA + (256 + u * 16) * W2T_STRIDE);
            #pragma unroll
            for (int q = 0; q < 4; q++) {
                float4 va = qA[q];
                wA0 = fmaf(h0r[4 * q + 0], va.x, wA0);
                wA0 = fmaf(h0r[4 * q + 1], va.y, wA0);
                wA0 = fmaf(h0r[4 * q + 2], va.z, wA0);
                wA0 = fmaf(h0r[4 * q + 3], va.w, wA0);
                wA1 = fmaf(h1r[4 * q + 0], va.x, wA1);
                wA1 = fmaf(h1r[4 * q + 1], va.y, wA1);
                wA1 = fmaf(h1r[4 * q + 2], va.z, wA1);
                wA1 = fmaf(h1r[4 * q + 3], va.w, wA1);
                float4 vb = qB[q];
                wB0 = fmaf(h0r[4 * q + 0], vb.x, wB0);
                wB0 = fmaf(h0r[4 * q + 1], vb.y, wB0);
                wB0 = fmaf(h0r[4 * q + 2], vb.z, wB0);
                wB0 = fmaf(h0r[4 * q + 3], vb.w, wB0);
                wB1 = fmaf(h1r[4 * q + 0], vb.x, wB1);
                wB1 = fmaf(h1r[4 * q + 1], vb.y, wB1);
                wB1 = fmaf(h1r[4 * q + 2], vb.z, wB1);
                wB1 = fmaf(h1r[4 * q + 3], vb.w, wB1);
            }
            a00 = fmaf(s00, wA0, a00);
            a10 = fmaf(s10, wB0, a10);
            a20 = fmaf(s20, wB0, a20);
            a30 = fmaf(s30, wB0, a30);
            a01 = fmaf(s01, wA1, a01);
            a11 = fmaf(s11, wB1, a11);
            a21 = fmaf(s21, wB1, a21);
            a31 = fmaf(s31, wB1, a31);
        }

        // ---- scatter-add ----
        float* o0 = out + (size_t)d0 * 64;
        float* o1 = out + (size_t)d1 * 64;
        if (!hi16) {
            atomicAdd(o0 + wv, alpha * fmaf(inv3, a10, a00));
            atomicAdd(o1 + wv, alpha * fmaf(inv3, a11, a01));
        } else {
            atomicAdd(o0 + 16 + 3 * wv + 0, alpha * fmaf(sh0.y, a00, sh0.x * a10));
            atomicAdd(o0 + 16 + 3 * wv + 1, alpha * fmaf(sh0.z, a00, sh0.x * a20));
            atomicAdd(o0 + 16 + 3 * wv + 2, alpha * fmaf(sh0.w, a00, sh0.x * a30));
            atomicAdd(o1 + 16 + 3 * wv + 0, alpha * fmaf(sh1.y, a01, sh1.x * a11));
            atomicAdd(o1 + 16 + 3 * wv + 1, alpha * fmaf(sh1.z, a01, sh1.x * a21));
            atomicAdd(o1 + 16 + 3 * wv + 2, alpha * fmaf(sh1.w, a01, sh1.x * a31));
        }
        if (lane < 2) {
            int dd = lane ? d1 : d0;
            atomicAdd(&g_counts[dd], 1.f);
        }
    }
}

__global__ void finalize_kernel(float* __restrict__ out) {
    int i = blockIdx.x * blockDim.x + threadIdx.x;
    if (i < OUT_ELEMS) {
        float c = fmaxf(g_counts[i >> 6], 1.f);
        out[i] = out[i] / c;
    }
}

extern "C" void kernel_launch(void* const* d_in, const int* in_sizes, int n_in,
                              void* d_out, int out_size) {
    const float* node_attr = (const float*)d_in[0];
    const void*  edge_index = d_in[1];
    const float* edge_attr = (const float*)d_in[2];
    const float* edge_sh   = (const float*)d_in[3];
    const float* w1 = (const float*)d_in[4];
    const float* b1 = (const float*)d_in[5];
    const float* w2 = (const float*)d_in[6];
    const float* b2 = (const float*)d_in[7];
    float* out = (float*)d_out;

    cudaFuncSetAttribute(conv_kernel, cudaFuncAttributeMaxDynamicSharedMemorySize,
                         SM_TOT * (int)sizeof(float));

    int smCount = 148;
    cudaDeviceGetAttribute(&smCount, cudaDevAttrMultiProcessorCount, 0);

    detect_kernel<<<1, 32>>>((const unsigned*)edge_index);
    prep_kernel<<<(OUT_ELEMS + 255) / 256, 256>>>((const int*)edge_index, out);
    conv_kernel<<<2 * smCount, 256, SM_TOT * (int)sizeof(float)>>>(
        node_attr, edge_attr, (const float4*)edge_sh, w1, b1, w2, b2, out);
    finalize_kernel<<<(OUT_ELEMS + 255) / 256, 256>>>(out);
}

// round 3
// speedup vs baseline: 1.0708x; 1.0708x over previous
#include <cuda_runtime.h>
#include <cmath>

#define N_NODES 12500
#define N_EDGES 200000
#define OUT_ELEMS (N_NODES * 64)

// shared memory layout (floats). stride 18: (18*w) mod 32 distinct for w=0..15
// -> conflict-free LDS.64 pair loads.
#define W2T_STRIDE 18
#define SM_W2T 0                          // 1024 rows * 18 = 18432 floats
#define SM_B2  (1024 * W2T_STRIDE)        // 18432
#define SM_TOT (SM_B2 + 1024)             // 19456 floats = 77824 bytes

__device__ int   g_src[N_EDGES];
__device__ int   g_dst[N_EDGES];
__device__ float g_counts[N_NODES];       // after invc_kernel: 1/max(count,1)
__device__ float g_h[N_EDGES * 16];       // precomputed silu(ea@w1+b1)
__device__ int   g_is64;

typedef unsigned long long ull;

__device__ __forceinline__ ull pack2(float lo, float hi) {
    ull r;
    asm("mov.b64 %0, {%1, %2};" : "=l"(r) : "f"(lo), "f"(hi));
    return r;
}
__device__ __forceinline__ ull fma2(ull a, ull b, ull c) {
    ull d;
    asm("fma.rn.f32x2 %0, %1, %2, %3;" : "=l"(d) : "l"(a), "l"(b), "l"(c));
    return d;
}
__device__ __forceinline__ float pairsum(ull v) {
    float lo, hi;
    asm("mov.b64 {%0, %1}, %2;" : "=f"(lo), "=f"(hi) : "l"(v));
    return lo + hi;
}

// ---------------------------------------------------------------------------
// k1: detect edge_index dtype + zero output and counts
// ---------------------------------------------------------------------------
__global__ void zero_kernel(const unsigned* __restrict__ ei, float* __restrict__ out) {
    int i = blockIdx.x * blockDim.x + threadIdx.x;
    if (i == 0) {
        int ok = 1;
        for (int j = 0; j < 128; j++) ok &= (ei[2 * j + 1] == 0u);
        g_is64 = ok;
    }
    if (i < OUT_ELEMS) out[i] = 0.f;
    if (i < N_NODES) g_counts[i] = 0.f;
}

// k2: convert edge_index to int32 scratch + accumulate dst counts
__global__ void prep_kernel(const int* __restrict__ ei) {
    int i = blockIdx.x * blockDim.x + threadIdx.x;
    if (i < N_EDGES) {
        int s, d;
        if (g_is64) { s = ei[2 * i]; d = ei[2 * (N_EDGES + i)]; }
        else        { s = ei[i];     d = ei[N_EDGES + i]; }
        g_src[i] = s;
        g_dst[i] = d;
        atomicAdd(&g_counts[d], 1.f);
    }
}

// k3: invert counts
__global__ void invc_kernel() {
    int i = blockIdx.x * blockDim.x + threadIdx.x;
    if (i < N_NODES) g_counts[i] = 1.f / fmaxf(g_counts[i], 1.f);
}

// k4: h = silu(edge_attr @ w1 + b1), one thread per edge
__global__ void h_kernel(const float* __restrict__ ea,
                         const float* __restrict__ w1g,
                         const float* __restrict__ b1g) {
    __shared__ float sw[256], sb[16];
    if (threadIdx.x < 256) sw[threadIdx.x] = w1g[threadIdx.x];
    if (threadIdx.x < 16)  sb[threadIdx.x] = b1g[threadIdx.x];
    __syncthreads();
    int e = blockIdx.x * blockDim.x + threadIdx.x;
    if (e >= N_EDGES) return;
    const float4* r = (const float4*)(ea + (size_t)e * 16);
    float4 v0 = r[0], v1 = r[1], v2 = r[2], v3 = r[3];
    float in[16] = {v0.x, v0.y, v0.z, v0.w, v1.x, v1.y, v1.z, v1.w,
                    v2.x, v2.y, v2.z, v2.w, v3.x, v3.y, v3.z, v3.w};
    float o[16];
    #pragma unroll
    for (int k = 0; k < 16; k++) {
        float t = sb[k];
        #pragma unroll
        for (int j = 0; j < 16; j++) t = fmaf(in[j], sw[j * 16 + k], t);
        o[k] = t / (1.f + __expf(-t));
    }
    float4* dst = (float4*)(g_h + (size_t)e * 16);
    dst[0] = make_float4(o[0], o[1], o[2], o[3]);
    dst[1] = make_float4(o[4], o[5], o[6], o[7]);
    dst[2] = make_float4(o[8], o[9], o[10], o[11]);
    dst[3] = make_float4(o[12], o[13], o[14], o[15]);
}

// k5: dummy so conv is the 6th launch (ncu -s 5 -c 1 profiles it)
__global__ void dummy_kernel() {}

// ---------------------------------------------------------------------------
// k6: main conv. One warp processes 4 edges per pass.
//   lane w = lane&15 owns output column w; lanes 0-15 -> weight blocks {0,1},
//   lanes 16-31 -> blocks {2,3}. k-contraction uses packed fp32x2 FMAs:
//   pairs (k, k+1) packed in 64-bit regs (h pairs from LDG.128 of g_h,
//   w2 pairs from LDS.64 of the transposed shared copy).
// ---------------------------------------------------------------------------
__global__ void __launch_bounds__(256) conv_kernel(
    const float*  __restrict__ node_attr,
    const float4* __restrict__ edge_sh4,
    const float*  __restrict__ w2,
    const float*  __restrict__ b2,
    float*        __restrict__ out)
{
    extern __shared__ float sm[];

    // stage w2 transposed to k-contiguous rows: w2t[j][k], j = b*256+u*16+w
    for (int i = threadIdx.x; i < 16 * 1024; i += 256) {
        int k = i >> 10, j = i & 1023;           // coalesced read of w2[k][j]
        sm[SM_W2T + j * W2T_STRIDE + k] = w2[i];
    }
    for (int i = threadIdx.x; i < 1024; i += 256) sm[SM_B2 + i] = b2[i];
    __syncthreads();

    const int lane = threadIdx.x & 31;
    const int wv   = lane & 15;
    const int hi16 = lane & 16;

    const float* pA  = sm + SM_W2T + (((hi16 ? 512 : 0)) + wv) * W2T_STRIDE;
    const float* b2A = sm + SM_B2 + (hi16 ? 512 : 0) + wv;

    const float alpha = 0.17677669529663688f;    // 1/sqrt(32)
    const float inv3  = 0.57735026918962576f;    // 1/sqrt(3)

    const int warpsTotal = gridDim.x * (blockDim.x >> 5);
    const int gw = blockIdx.x * (blockDim.x >> 5) + (threadIdx.x >> 5);

    for (int p = gw; p < N_EDGES / 4; p += warpsTotal) {
        const int e0 = 4 * p;

        int s[4], d[4];
        #pragma unroll
        for (int q = 0; q < 4; q++) { s[q] = g_src[e0 + q]; d[q] = g_dst[e0 + q]; }

        // h pairs: (h[2m], h[2m+1]) packed, straight from LDG.128
        ull hp[4][8];
        #pragma unroll
        for (int q = 0; q < 4; q++) {
            const ulonglong2* gh = (const ulonglong2*)(g_h + (size_t)(e0 + q) * 16);
            ulonglong2 ga = gh[0], gb = gh[1], gc = gh[2], gd = gh[3];
            hp[q][0] = ga.x; hp[q][1] = ga.y; hp[q][2] = gb.x; hp[q][3] = gb.y;
            hp[q][4] = gc.x; hp[q][5] = gc.y; hp[q][6] = gd.x; hp[q][7] = gd.y;
        }

        // gather node features, build per-u coefficient registers (shfl sources)
        float rA[4], rB1[4], rB2[4], rB3[4];
        #pragma unroll
        for (int q = 0; q < 4; q++) {
            float4 sh = edge_sh4[e0 + q];
            const float* n = node_attr + (size_t)s[q] * 64;
            float x0 = n[wv];
            float xa = n[16 + 3 * wv], xb = n[17 + 3 * wv], xc = n[18 + 3 * wv];
            if (hi16) { rA[q] = x0;        rB1[q] = xa; rB2[q] = xb; rB3[q] = xc; }
            else      { rA[q] = x0 * sh.x;
                        rB1[q] = fmaf(xa, sh.y, fmaf(xb, sh.z, xc * sh.w));
                        rB2[q] = 0.f; rB3[q] = 0.f; }
        }

        float a0[4] = {0.f, 0.f, 0.f, 0.f};
        float a1[4] = {0.f, 0.f, 0.f, 0.f};
        float a2[4] = {0.f, 0.f, 0.f, 0.f};
        float a3[4] = {0.f, 0.f, 0.f, 0.f};

        #pragma unroll 1
        for (int u = 0; u < 16; u++) {
            const int srcLane = u + hi16;
            float s0[4], s1[4], s2[4], s3[4];
            #pragma unroll
            for (int q = 0; q < 4; q++) {
                s0[q] = __shfl_sync(0xffffffffu, rA[q],  srcLane);
                s1[q] = __shfl_sync(0xffffffffu, rB1[q], srcLane);
                s2[q] = __shfl_sync(0xffffffffu, rB2[q], srcLane);
                s3[q] = __shfl_sync(0xffffffffu, rB3[q], srcLane);
            }

            float bA = b2A[u * 16];
            float bB = b2A[256 + u * 16];
            ull iA = pack2(bA, 0.f);
            ull iB = pack2(bB, 0.f);

            const ull* qA = (const ull*)(pA + u * 16 * W2T_STRIDE);
            const ull* qB = (const ull*)(pA + (256 + u * 16) * W2T_STRIDE);

            ull accA[4] = {iA, iA, iA, iA};
            ull accB[4] = {iB, iB, iB, iB};
            #pragma unroll
            for (int m = 0; m < 8; m++) {
                ull wAm = qA[m];
                ull wBm = qB[m];
                #pragma unroll
                for (int q = 0; q < 4; q++) {
                    accA[q] = fma2(hp[q][m], wAm, accA[q]);
                    accB[q] = fma2(hp[q][m], wBm, accB[q]);
                }
            }
            #pragma unroll
            for (int q = 0; q < 4; q++) {
                float wA = pairsum(accA[q]);
                float wB = pairsum(accB[q]);
                a0[q] = fmaf(s0[q], wA, a0[q]);
                a1[q] = fmaf(s1[q], wB, a1[q]);
                a2[q] = fmaf(s2[q], wB, a2[q]);
                a3[q] = fmaf(s3[q], wB, a3[q]);
            }
        }

        // scatter-add with pre-folded alpha / count
        #pragma unroll
        for (int q = 0; q < 4; q++) {
            float scale = alpha * g_counts[d[q]];
            float* o = out + (size_t)d[q] * 64;
            if (!hi16) {
                atomicAdd(o + wv, scale * fmaf(inv3, a1[q], a0[q]));
            } else {
                float4 sh = edge_sh4[e0 + q];
                atomicAdd(o + 16 + 3 * wv + 0, scale * fmaf(sh.y, a0[q], sh.x * a1[q]));
                atomicAdd(o + 16 + 3 * wv + 1, scale * fmaf(sh.z, a0[q], sh.x * a2[q]));
                atomicAdd(o + 16 + 3 * wv + 2, scale * fmaf(sh.w, a0[q], sh.x * a3[q]));
            }
        }
    }
}

extern "C" void kernel_launch(void* const* d_in, const int* in_sizes, int n_in,
                              void* d_out, int out_size) {
    const float* node_attr  = (const float*)d_in[0];
    const void*  edge_index = d_in[1];
    const float* edge_attr  = (const float*)d_in[2];
    const float* edge_sh    = (const float*)d_in[3];
    const float* w1 = (const float*)d_in[4];
    const float* b1 = (const float*)d_in[5];
    const float* w2 = (const float*)d_in[6];
    const float* b2 = (const float*)d_in[7];
    float* out = (float*)d_out;

    cudaFuncSetAttribute(conv_kernel, cudaFuncAttributeMaxDynamicSharedMemorySize,
                         SM_TOT * (int)sizeof(float));

    int smCount = 148;
    cudaDeviceGetAttribute(&smCount, cudaDevAttrMultiProcessorCount, 0);

    zero_kernel<<<(OUT_ELEMS + 255) / 256, 256>>>((const unsigned*)edge_index, out);
    prep_kernel<<<(N_EDGES + 255) / 256, 256>>>((const int*)edge_index);
    invc_kernel<<<(N_NODES + 255) / 256, 256>>>();
    h_kernel<<<(N_EDGES + 255) / 256, 256>>>(edge_attr, w1, b1);
    dummy_kernel<<<1, 32>>>();
    conv_kernel<<<2 * smCount, 256, SM_TOT * (int)sizeof(float)>>>(
        node_attr, (const float4*)edge_sh, w2, b2, out);
}